// round 2
// baseline (speedup 1.0000x reference)
#include <cuda_runtime.h>
#include <cuda_bf16.h>
#include <cstdint>

// ---------------- static device scratch (no allocs allowed) ----------------
#define MAXR   32
#define EPB    4096
#define MAXBLK 1024
#define MAXE   2000000

__device__ int g_blockhist[MAXBLK * MAXR];
__device__ int g_blockbase[MAXBLK * MAXR];
__device__ int g_off[MAXR + 1];
__device__ int g_ts[MAXR + 1];
__device__ int g_perm[MAXE];
// Pre-packed B fragments (mma.m16n8k16 register order), hi/lo bf16 split.
// Layout: [rel][ks(4)][nt(8)][lane(32)] -> uint2 {b0b1, b2b3}
__device__ __align__(16) uint2 g_wfhi[MAXR * 1024];
__device__ __align__(16) uint2 g_wflo[MAXR * 1024];

// ---------------- helpers ----------------
__device__ __forceinline__ uint32_t smem_u32(const void* p) {
    uint32_t a;
    asm("{ .reg .u64 t; cvta.to.shared.u64 t, %1; cvt.u32.u64 %0, t; }"
        : "=r"(a) : "l"(p));
    return a;
}

__device__ __forceinline__ uint32_t pack_bf2(__nv_bfloat16 a, __nv_bfloat16 b) {
    __nv_bfloat162 t = __halves2bfloat162(a, b);
    return *reinterpret_cast<uint32_t*>(&t);
}

__device__ __forceinline__ void split2(float x, float y, uint32_t& hi, uint32_t& lo) {
    __nv_bfloat16 hx = __float2bfloat16(x), hy = __float2bfloat16(y);
    __nv_bfloat16 lx = __float2bfloat16(x - __bfloat162float(hx));
    __nv_bfloat16 ly = __float2bfloat16(y - __bfloat162float(hy));
    hi = pack_bf2(hx, hy);
    lo = pack_bf2(lx, ly);
}

__device__ __forceinline__ void mma16816(float* c, const uint32_t* a, const uint32_t* b) {
    asm volatile(
        "mma.sync.aligned.m16n8k16.row.col.f32.bf16.bf16.f32 "
        "{%0,%1,%2,%3}, {%4,%5,%6,%7}, {%8,%9}, {%0,%1,%2,%3};"
        : "+f"(c[0]), "+f"(c[1]), "+f"(c[2]), "+f"(c[3])
        : "r"(a[0]), "r"(a[1]), "r"(a[2]), "r"(a[3]), "r"(b[0]), "r"(b[1]));
}

__device__ __forceinline__ void ldsm4(uint32_t* r, uint32_t addr) {
    asm volatile("ldmatrix.sync.aligned.m8n8.x4.shared.b16 {%0,%1,%2,%3}, [%4];"
                 : "=r"(r[0]), "=r"(r[1]), "=r"(r[2]), "=r"(r[3]) : "r"(addr));
}

__device__ __forceinline__ void red4(float* p, float a, float b, float c, float d) {
    asm volatile("red.global.add.v4.f32 [%0], {%1, %2, %3, %4};"
                 :: "l"(p), "f"(a), "f"(b), "f"(c), "f"(d) : "memory");
}

// ---------------- prep: W -> bf16 hi/lo B-fragments in mma register order ----
// Output-column permutation: fragment (nt, phys col p) holds logical column
// L = (p>>1)*16 + nt*2 + (p&1), so that each thread's C fragments own 16
// CONSECUTIVE logical columns -> v4 reductions in the epilogue.
__global__ void k_prepw(const float* __restrict__ w) {
    int r = blockIdx.x;
    const float* wr = w + r * 4096;
    for (int idx = threadIdx.x; idx < 1024; idx += blockDim.x) {
        int t = idx & 31, nt = (idx >> 5) & 7, ks = idx >> 8;
        int m = t & 3, p = t >> 2;
        int n = (p >> 1) * 16 + nt * 2 + (p & 1);   // logical output column
        int k0 = ks * 16 + 2 * m;
        float w00 = wr[k0 * 64 + n],       w01 = wr[(k0 + 1) * 64 + n];
        float w10 = wr[(k0 + 8) * 64 + n], w11 = wr[(k0 + 9) * 64 + n];
        uint32_t h0, l0, h1, l1;
        split2(w00, w01, h0, l0);
        split2(w10, w11, h1, l1);
        g_wfhi[r * 1024 + idx] = make_uint2(h0, h1);
        g_wflo[r * 1024 + idx] = make_uint2(l0, l1);
    }
}

// ---------------- counting sort by relation ----------------
__global__ void k_blockhist(const int* __restrict__ et, int E) {
    __shared__ int h[MAXR];
    if (threadIdx.x < MAXR) h[threadIdx.x] = 0;
    __syncthreads();
    int start = blockIdx.x * EPB, end = min(start + EPB, E);
    for (int i = start + threadIdx.x; i < end; i += blockDim.x)
        atomicAdd(&h[et[i]], 1);
    __syncthreads();
    if (threadIdx.x < MAXR)
        g_blockhist[blockIdx.x * MAXR + threadIdx.x] = h[threadIdx.x];
}

__global__ void k_scan(int nblocks, int R) {
    __shared__ int tot[MAXR], off[MAXR + 1];
    int r = threadIdx.x;
    int s = 0;
    if (r < R)
        for (int b = 0; b < nblocks; b++) s += g_blockhist[b * MAXR + r];
    if (r < MAXR) tot[r] = s;
    __syncwarp();
    if (r == 0) {
        int acc = 0;
        for (int i = 0; i < R; i++) { off[i] = acc; acc += tot[i]; }
        off[R] = acc;
        int ts = 0;
        for (int i = 0; i < R; i++) { g_ts[i] = ts; ts += (tot[i] + 127) >> 7; }
        g_ts[R] = ts;
        for (int i = 0; i <= R; i++) g_off[i] = off[i];
    }
    __syncwarp();
    if (r < R) {
        int base = off[r];
        for (int b = 0; b < nblocks; b++) {
            g_blockbase[b * MAXR + r] = base;
            base += g_blockhist[b * MAXR + r];
        }
    }
}

__global__ void k_scatter(const int* __restrict__ et, int E) {
    __shared__ int cur[MAXR];
    if (threadIdx.x < MAXR)
        cur[threadIdx.x] = g_blockbase[blockIdx.x * MAXR + threadIdx.x];
    __syncthreads();
    int start = blockIdx.x * EPB, end = min(start + EPB, E);
    for (int i = start + threadIdx.x; i < end; i += blockDim.x) {
        int p = atomicAdd(&cur[et[i]], 1);
        g_perm[p] = i;
    }
}

// ---------------- main: gather -> HMMA (bf16 3-term) -> red.v4 scatter ------
// SMEM: A_hi 128x128B (XOR-swizzled 16B chunks), A_lo same, B frag hi/lo 8KB
// each, dst[128], ctrl[4].
#define SM_AHI  0
#define SM_ALO  16384
#define SM_BH   32768
#define SM_BL   40960
#define SM_DST  49152
#define SM_CTRL 49664
#define SMEM_SZ 49696

__global__ __launch_bounds__(256, 3) void k_main(
    const float* __restrict__ feat, const int* __restrict__ src,
    const int* __restrict__ dst, float* __restrict__ out, int R)
{
    extern __shared__ char smem[];
    int tid = threadIdx.x;

    if ((int)blockIdx.x >= g_ts[R]) return;

    int* ctrl = (int*)(smem + SM_CTRL);
    if (tid == 0) {
        int b = blockIdx.x, r = 0;
        while (b >= g_ts[r + 1]) r++;
        int beg = g_off[r] + (b - g_ts[r]) * 128;
        ctrl[0] = r;
        ctrl[1] = beg;
        ctrl[2] = min(128, g_off[r + 1] - beg);
    }
    __syncthreads();
    int rel = ctrl[0], base = ctrl[1], cnt = ctrl[2];

    if (tid < 128) {
        // gather + hi/lo split: thread = A row
        int row = tid;
        char* ah = smem + SM_AHI + row * 128;
        char* al = smem + SM_ALO + row * 128;
        int sw = row & 7;
        if (row < cnt) {
            int e = g_perm[base + row];
            int s = src[e];
            ((int*)(smem + SM_DST))[row] = dst[e];
            const float4* f4 = (const float4*)(feat + (size_t)s * 64);
#pragma unroll
            for (int c = 0; c < 8; c++) {
                float4 va = f4[2 * c], vb = f4[2 * c + 1];
                uint4 hv, lv;
                split2(va.x, va.y, hv.x, lv.x);
                split2(va.z, va.w, hv.y, lv.y);
                split2(vb.x, vb.y, hv.z, lv.z);
                split2(vb.z, vb.w, hv.w, lv.w);
                int off = (c ^ sw) << 4;
                *(uint4*)(ah + off) = hv;
                *(uint4*)(al + off) = lv;
            }
        } else {
            ((int*)(smem + SM_DST))[row] = 0;
            uint4 z = make_uint4(0, 0, 0, 0);
#pragma unroll
            for (int c = 0; c < 8; c++) {
                int off = (c ^ sw) << 4;
                *(uint4*)(ah + off) = z;
                *(uint4*)(al + off) = z;
            }
        }
    } else {
        // copy this relation's pre-packed B fragments (8KB hi + 8KB lo)
        int t = tid - 128;
        const uint4* wh = (const uint4*)(g_wfhi + (size_t)rel * 1024);
        const uint4* wl = (const uint4*)(g_wflo + (size_t)rel * 1024);
        uint4* bh = (uint4*)(smem + SM_BH);
        uint4* bl = (uint4*)(smem + SM_BL);
#pragma unroll
        for (int i = 0; i < 4; i++) {
            bh[t + 128 * i] = wh[t + 128 * i];
            bl[t + 128 * i] = wl[t + 128 * i];
        }
    }
    __syncthreads();

    // ---- compute: warp w handles rows [16w, 16w+16), all 64 cols ----
    int w = tid >> 5, lane = tid & 31;
    int rbase = w * 16;

    float acc[8][4];
#pragma unroll
    for (int nt = 0; nt < 8; nt++)
#pragma unroll
        for (int j = 0; j < 4; j++) acc[nt][j] = 0.0f;

    uint32_t sbase = smem_u32(smem);
    int trow = lane & 7;
    int thalf = (lane >> 3) & 1;
    int tchunk = lane >> 4;                 // 0 or 1 (k-halves)
    int arow = rbase + thalf * 8 + trow;

#pragma unroll
    for (int ks = 0; ks < 4; ks++) {
        int chunk = (2 * ks + tchunk) ^ (arow & 7);
        uint32_t ahaddr = sbase + SM_AHI + arow * 128 + chunk * 16;
        uint32_t ahi[4], alo[4];
        ldsm4(ahi, ahaddr);
        ldsm4(alo, ahaddr + 16384);
        const uint2* bh = (const uint2*)(smem + SM_BH) + ks * 256 + lane;
        const uint2* bl = (const uint2*)(smem + SM_BL) + ks * 256 + lane;
#pragma unroll
        for (int nt = 0; nt < 8; nt++) {
            uint2 b0 = bh[nt * 32];
            uint2 b1 = bl[nt * 32];
            mma16816(acc[nt], ahi, (const uint32_t*)&b0);   // Fh*Wh
            mma16816(acc[nt], alo, (const uint32_t*)&b0);   // Fl*Wh
            mma16816(acc[nt], ahi, (const uint32_t*)&b1);   // Fh*Wl
        }
    }

    // ---- epilogue: thread owns cols [m*16, m*16+16) of rows r0, r0+8 ----
    int m = lane & 3, p = lane >> 2;
    int r0 = rbase + p, r1 = r0 + 8;
    int d0 = ((int*)(smem + SM_DST))[r0];
    int d1 = ((int*)(smem + SM_DST))[r1];
    float* o0 = out + (size_t)d0 * 64 + m * 16;
    float* o1 = out + (size_t)d1 * 64 + m * 16;
    bool v0 = r0 < cnt, v1 = r1 < cnt;
#pragma unroll
    for (int q = 0; q < 4; q++) {
        if (v0) red4(o0 + 4 * q, acc[2 * q][0], acc[2 * q][1],
                     acc[2 * q + 1][0], acc[2 * q + 1][1]);
        if (v1) red4(o1 + 4 * q, acc[2 * q][2], acc[2 * q][3],
                     acc[2 * q + 1][2], acc[2 * q + 1][3]);
    }
}

// ---------------- launch ----------------
extern "C" void kernel_launch(void* const* d_in, const int* in_sizes, int n_in,
                              void* d_out, int out_size) {
    const float* feat   = (const float*)d_in[0];
    const float* weight = (const float*)d_in[1];
    const int*   src    = (const int*)d_in[2];
    const int*   dst    = (const int*)d_in[3];
    const int*   et     = (const int*)d_in[4];

    int E = in_sizes[2];
    int R = in_sizes[1] / 4096;   // 64*64 per relation
    float* out = (float*)d_out;

    cudaMemsetAsync(out, 0, (size_t)out_size * sizeof(float), 0);

    k_prepw<<<R, 256>>>(weight);

    int nblocks = (E + EPB - 1) / EPB;
    k_blockhist<<<nblocks, 256>>>(et, E);
    k_scan<<<1, 32>>>(nblocks, R);
    k_scatter<<<nblocks, 256>>>(et, E);

    int ntiles = (E + 127) / 128 + R;   // upper bound; extras exit via g_ts[R]
    static int smem_set = 0;
    if (!smem_set) {
        cudaFuncSetAttribute(k_main, cudaFuncAttributeMaxDynamicSharedMemorySize, SMEM_SZ);
        smem_set = 1;
    }
    k_main<<<ntiles, 256, SMEM_SZ>>>(feat, src, dst, out, R);
}

// round 3
// speedup vs baseline: 1.0984x; 1.0984x over previous
#include <cuda_runtime.h>
#include <cuda_bf16.h>
#include <cstdint>

// ---------------- static device scratch (no allocs allowed) ----------------
#define MAXR   32
#define EPB    4096
#define MAXBLK 1024
#define MAXE   2000000

__device__ int g_blockhist[MAXBLK * MAXR];
__device__ int g_blockbase[MAXBLK * MAXR];
__device__ int g_off[MAXR + 1];   // edge offsets per relation
__device__ int g_gs[MAXR + 1];    // group (4-tile) offsets per relation
__device__ int2 g_srcdst[MAXE];   // packed {src, dst} in relation-sorted order
// Pre-packed B fragments (mma.m16n8k16 register order), bf16 hi/lo split.
// Layout: [rel][ks(4)][ntg(8)][lane(32)] -> uint2 {b0, b1}
__device__ __align__(16) uint2 g_wfh[MAXR * 1024];
__device__ __align__(16) uint2 g_wfl[MAXR * 1024];

// ---------------- helpers ----------------
__device__ __forceinline__ uint32_t smem_u32(const void* p) {
    uint32_t a;
    asm("{ .reg .u64 t; cvta.to.shared.u64 t, %1; cvt.u32.u64 %0, t; }"
        : "=r"(a) : "l"(p));
    return a;
}

__device__ __forceinline__ uint32_t pack_bf2(__nv_bfloat16 a, __nv_bfloat16 b) {
    __nv_bfloat162 t = __halves2bfloat162(a, b);
    return *reinterpret_cast<uint32_t*>(&t);
}

__device__ __forceinline__ uint32_t prmt7632(uint32_t a, uint32_t b) {
    uint32_t d;
    asm("prmt.b32 %0, %1, %2, 0x7632;" : "=r"(d) : "r"(a), "r"(b));
    return d;
}

// truncate-split of an fp32 pair into bf16x2 hi (exact truncation) + lo (rn)
__device__ __forceinline__ void tsplit(float x, float y, uint32_t& hi, uint32_t& lo) {
    uint32_t xi = __float_as_uint(x), yi = __float_as_uint(y);
    hi = prmt7632(xi, yi);
    float hx = __uint_as_float(xi & 0xFFFF0000u);
    float hy = __uint_as_float(yi & 0xFFFF0000u);
    __nv_bfloat162 l2 = __floats2bfloat162_rn(x - hx, y - hy);
    lo = *reinterpret_cast<uint32_t*>(&l2);
}

__device__ __forceinline__ void mma16816(float* c, const uint32_t* a, const uint32_t* b) {
    asm volatile(
        "mma.sync.aligned.m16n8k16.row.col.f32.bf16.bf16.f32 "
        "{%0,%1,%2,%3}, {%4,%5,%6,%7}, {%8,%9}, {%0,%1,%2,%3};"
        : "+f"(c[0]), "+f"(c[1]), "+f"(c[2]), "+f"(c[3])
        : "r"(a[0]), "r"(a[1]), "r"(a[2]), "r"(a[3]), "r"(b[0]), "r"(b[1]));
}

__device__ __forceinline__ void red4(float* p, float a, float b, float c, float d) {
    asm volatile("red.global.add.v4.f32 [%0], {%1, %2, %3, %4};"
                 :: "l"(p), "f"(a), "f"(b), "f"(c), "f"(d) : "memory");
}

__device__ __forceinline__ void cpasync16(uint32_t dst, const void* src) {
    asm volatile("cp.async.ca.shared.global [%0], [%1], 16;"
                 :: "r"(dst), "l"(src) : "memory");
}
#define CP_COMMIT() asm volatile("cp.async.commit_group;" ::: "memory")
#define CP_WAIT(N)  asm volatile("cp.async.wait_group %0;" :: "n"(N) : "memory")

// ---------------- prep: W -> bf16 hi/lo B-fragments in mma register order ----
// Logical output column for (warp-half h, nt, phys col q):
//   n = h*32 + (q>>1)*8 + nt*2 + (q&1)
// so each compute thread's C fragments own 8 consecutive logical columns.
__global__ void k_prepw(const float* __restrict__ w) {
    int r = blockIdx.x;
    const float* wr = w + r * 4096;
    for (int idx = threadIdx.x; idx < 1024; idx += blockDim.x) {
        int lane = idx & 31, ntg = (idx >> 5) & 7, ks = idx >> 8;
        int h = ntg >> 2, nt = ntg & 3, q = lane >> 2;
        int n = h * 32 + (q >> 1) * 8 + nt * 2 + (q & 1);
        int k0 = ks * 16 + 2 * (lane & 3);
        float w00 = wr[k0 * 64 + n],       w01 = wr[(k0 + 1) * 64 + n];
        float w10 = wr[(k0 + 8) * 64 + n], w11 = wr[(k0 + 9) * 64 + n];
        __nv_bfloat16 h00 = __float2bfloat16(w00), h01 = __float2bfloat16(w01);
        __nv_bfloat16 h10 = __float2bfloat16(w10), h11 = __float2bfloat16(w11);
        __nv_bfloat16 l00 = __float2bfloat16(w00 - __bfloat162float(h00));
        __nv_bfloat16 l01 = __float2bfloat16(w01 - __bfloat162float(h01));
        __nv_bfloat16 l10 = __float2bfloat16(w10 - __bfloat162float(h10));
        __nv_bfloat16 l11 = __float2bfloat16(w11 - __bfloat162float(h11));
        g_wfh[r * 1024 + idx] = make_uint2(pack_bf2(h00, h01), pack_bf2(h10, h11));
        g_wfl[r * 1024 + idx] = make_uint2(pack_bf2(l00, l01), pack_bf2(l10, l11));
    }
}

// ---------------- counting sort by relation ----------------
__global__ void k_blockhist(const int* __restrict__ et, int E) {
    __shared__ int h[MAXR];
    if (threadIdx.x < MAXR) h[threadIdx.x] = 0;
    __syncthreads();
    int start = blockIdx.x * EPB, end = min(start + EPB, E);
    for (int i = start + threadIdx.x; i < end; i += blockDim.x)
        atomicAdd(&h[et[i]], 1);
    __syncthreads();
    if (threadIdx.x < MAXR)
        g_blockhist[blockIdx.x * MAXR + threadIdx.x] = h[threadIdx.x];
}

__global__ void k_scan(int nblocks, int R) {
    __shared__ int tot[MAXR], off[MAXR + 1];
    int r = threadIdx.x;
    int s = 0;
    if (r < R)
        for (int b = 0; b < nblocks; b++) s += g_blockhist[b * MAXR + r];
    if (r < MAXR) tot[r] = s;
    __syncwarp();
    if (r == 0) {
        int acc = 0;
        for (int i = 0; i < R; i++) { off[i] = acc; acc += tot[i]; }
        off[R] = acc;
        int gs = 0;
        for (int i = 0; i < R; i++) {
            g_gs[i] = gs;
            int tiles = (tot[i] + 127) >> 7;
            gs += (tiles + 3) >> 2;           // groups of 4 tiles
        }
        g_gs[R] = gs;
        for (int i = 0; i <= R; i++) g_off[i] = off[i];
    }
    __syncwarp();
    if (r < R) {
        int base = off[r];
        for (int b = 0; b < nblocks; b++) {
            g_blockbase[b * MAXR + r] = base;
            base += g_blockhist[b * MAXR + r];
        }
    }
}

__global__ void k_scatter(const int* __restrict__ et, const int* __restrict__ src,
                          const int* __restrict__ dst, int E) {
    __shared__ int cur[MAXR];
    if (threadIdx.x < MAXR)
        cur[threadIdx.x] = g_blockbase[blockIdx.x * MAXR + threadIdx.x];
    __syncthreads();
    int start = blockIdx.x * EPB, end = min(start + EPB, E);
    for (int i = start + threadIdx.x; i < end; i += blockDim.x) {
        int p = atomicAdd(&cur[et[i]], 1);
        g_srcdst[p] = make_int2(src[i], dst[i]);
    }
}

// ---------------- main ----------------
// SMEM: A double-buffered raw fp32, row pitch 72 floats (288B, conflict-free
// for the frag LDS.64 pattern); B-frag hi+lo 16KB; dst double-buffered; ctrl.
#define APITCH  288               // bytes per A row (72 floats)
#define SM_A0   0                 // 128*288 = 36864
#define SM_A1   36864
#define SM_B    73728             // hi 8192 + lo 8192
#define SM_DST0 90112
#define SM_DST1 90624
#define SM_CTRL 91136
#define SMEM_SZ 91200

__global__ __launch_bounds__(256, 2) void k_main(
    const float* __restrict__ feat, float* __restrict__ out, int R)
{
    extern __shared__ char smem[];
    int tid = threadIdx.x;

    if ((int)blockIdx.x >= g_gs[R]) return;

    uint32_t sbase = smem_u32(smem);
    int* ctrl = (int*)(smem + SM_CTRL);
    if (tid == 0) {
        int b = blockIdx.x, r = 0;
        while (b >= g_gs[r + 1]) r++;
        int tile0 = (b - g_gs[r]) * 4;
        int ebase = g_off[r] + tile0 * 128;
        int erem = g_off[r + 1] - ebase;
        ctrl[0] = r;
        ctrl[1] = ebase;
        ctrl[2] = erem;
        ctrl[3] = min(4, (erem + 127) >> 7);
    }
    __syncthreads();
    int rel = ctrl[0], ebase = ctrl[1], erem = ctrl[2], ntile = ctrl[3];

    // ---- prologue: B frags + tile-0 gather in one cp.async group ----
    {
        const char* gh = (const char*)(g_wfh + (size_t)rel * 1024);
        const char* gl = (const char*)(g_wfl + (size_t)rel * 1024);
        uint32_t sB = sbase + SM_B;
#pragma unroll
        for (int i = 0; i < 2; i++) {
            int o = (tid + 256 * i) * 16;
            cpasync16(sB + o, gh + o);
            cpasync16(sB + 8192 + o, gl + o);
        }
    }
    {
        int row = tid >> 1, half = tid & 1;
        int cnt0 = min(128, erem);
        uint32_t sa = sbase + SM_A0 + row * APITCH + half * 128;
        if (row < cnt0) {
            int2 e = g_srcdst[ebase + row];
            if (half == 0) ((int*)(smem + SM_DST0))[row] = e.y;
            const char* gp = (const char*)(feat + (size_t)e.x * 64) + half * 128;
#pragma unroll
            for (int i = 0; i < 8; i++) cpasync16(sa + i * 16, gp + i * 16);
        } else {
            if (half == 0) ((int*)(smem + SM_DST0))[row] = 0;
            uint4 z = make_uint4(0, 0, 0, 0);
#pragma unroll
            for (int i = 0; i < 8; i++)
                *(uint4*)(smem + SM_A0 + row * APITCH + half * 128 + i * 16) = z;
        }
    }
    CP_COMMIT();

    int w = tid >> 5, lane = tid & 31;
    int mrow = (w & 3) * 32, h = w >> 2;
    int q = lane >> 2, m = lane & 3;

    for (int t = 0; t < ntile; t++) {
        int cnt = min(128, erem - t * 128);
        int abuf = (t & 1) ? SM_A1 : SM_A0;
        int dbuf = (t & 1) ? SM_DST1 : SM_DST0;

        // prefetch tile t+1 into the other buffer
        if (t + 1 < ntile) {
            int nbuf = ((t + 1) & 1) ? SM_A1 : SM_A0;
            int ndst = ((t + 1) & 1) ? SM_DST1 : SM_DST0;
            int cnt1 = min(128, erem - (t + 1) * 128);
            int row = tid >> 1, half = tid & 1;
            uint32_t sa = sbase + nbuf + row * APITCH + half * 128;
            if (row < cnt1) {
                int2 e = g_srcdst[ebase + (t + 1) * 128 + row];
                if (half == 0) ((int*)(smem + ndst))[row] = e.y;
                const char* gp = (const char*)(feat + (size_t)e.x * 64) + half * 128;
#pragma unroll
                for (int i = 0; i < 8; i++) cpasync16(sa + i * 16, gp + i * 16);
            } else {
                if (half == 0) ((int*)(smem + ndst))[row] = 0;
                uint4 z = make_uint4(0, 0, 0, 0);
#pragma unroll
                for (int i = 0; i < 8; i++)
                    *(uint4*)(smem + nbuf + row * APITCH + half * 128 + i * 16) = z;
            }
            CP_COMMIT();
            CP_WAIT(1);     // tile t's group (and B) complete
        } else {
            CP_WAIT(0);
        }
        __syncthreads();

        // ---- compute: warp tile 32 rows x 32 cols ----
        float acc[2][4][4];
#pragma unroll
        for (int a = 0; a < 2; a++)
#pragma unroll
            for (int b = 0; b < 4; b++)
#pragma unroll
                for (int c = 0; c < 4; c++) acc[a][b][c] = 0.0f;

        const char* Ab = smem + abuf;
#pragma unroll
        for (int ks = 0; ks < 4; ks++) {
            // B frags for this warp's 4 nt tiles (hi and lo)
            uint2 bh[4], bl[4];
            const uint2* Bp = (const uint2*)(smem + SM_B) + (ks * 8 + h * 4) * 32 + lane;
            const uint2* Blp = (const uint2*)(smem + SM_B + 8192) + (ks * 8 + h * 4) * 32 + lane;
#pragma unroll
            for (int nt = 0; nt < 4; nt++) { bh[nt] = Bp[nt * 32]; bl[nt] = Blp[nt * 32]; }

            int cb = (ks * 16 + 2 * m) * 4;
#pragma unroll
            for (int mt = 0; mt < 2; mt++) {
                int r = mrow + mt * 16 + q;
                float2 p00 = *(const float2*)(Ab + r * APITCH + cb);
                float2 p10 = *(const float2*)(Ab + (r + 8) * APITCH + cb);
                float2 p01 = *(const float2*)(Ab + r * APITCH + cb + 32);
                float2 p11 = *(const float2*)(Ab + (r + 8) * APITCH + cb + 32);
                uint32_t ahi[4], alo[4];
                tsplit(p00.x, p00.y, ahi[0], alo[0]);
                tsplit(p10.x, p10.y, ahi[1], alo[1]);
                tsplit(p01.x, p01.y, ahi[2], alo[2]);
                tsplit(p11.x, p11.y, ahi[3], alo[3]);
#pragma unroll
                for (int nt = 0; nt < 4; nt++) {
                    mma16816(acc[mt][nt], ahi, (const uint32_t*)&bh[nt]);  // Fh*Wh
                    mma16816(acc[mt][nt], alo, (const uint32_t*)&bh[nt]);  // Fl*Wh
                    mma16816(acc[mt][nt], ahi, (const uint32_t*)&bl[nt]);  // Fh*Wl
                }
            }
        }

        // ---- epilogue: 8 red.v4 per thread, 8 consecutive cols per row ----
        const int* db = (const int*)(smem + dbuf);
#pragma unroll
        for (int mt = 0; mt < 2; mt++)
#pragma unroll
            for (int hf = 0; hf < 2; hf++) {
                int row = mrow + mt * 16 + hf * 8 + q;
                if (row < cnt) {
                    int j = hf * 2;
                    float* o = out + (size_t)db[row] * 64 + h * 32 + m * 8;
                    red4(o,     acc[mt][0][j], acc[mt][0][j + 1],
                                acc[mt][1][j], acc[mt][1][j + 1]);
                    red4(o + 4, acc[mt][2][j], acc[mt][2][j + 1],
                                acc[mt][3][j], acc[mt][3][j + 1]);
                }
            }
        __syncthreads();   // buffer free before next prefetch overwrites it
    }
}

// ---------------- launch ----------------
extern "C" void kernel_launch(void* const* d_in, const int* in_sizes, int n_in,
                              void* d_out, int out_size) {
    const float* feat   = (const float*)d_in[0];
    const float* weight = (const float*)d_in[1];
    const int*   src    = (const int*)d_in[2];
    const int*   dst    = (const int*)d_in[3];
    const int*   et     = (const int*)d_in[4];

    int E = in_sizes[2];
    int R = in_sizes[1] / 4096;   // 64*64 per relation
    float* out = (float*)d_out;

    cudaMemsetAsync(out, 0, (size_t)out_size * sizeof(float), 0);

    k_prepw<<<R, 256>>>(weight);

    int nblocks = (E + EPB - 1) / EPB;
    k_blockhist<<<nblocks, 256>>>(et, E);
    k_scan<<<1, 32>>>(nblocks, R);
    k_scatter<<<nblocks, 256>>>(et, src, dst, E);

    int ngroups = (E + 511) / 512 + R;   // upper bound; extras exit via g_gs[R]
    static int smem_set = 0;
    if (!smem_set) {
        cudaFuncSetAttribute(k_main, cudaFuncAttributeMaxDynamicSharedMemorySize, SMEM_SZ);
        smem_set = 1;
    }
    k_main<<<ngroups, 256, SMEM_SZ>>>(feat, out, R);
}

// round 4
// speedup vs baseline: 1.5760x; 1.4348x over previous
#include <cuda_runtime.h>
#include <cuda_bf16.h>
#include <cuda_fp16.h>
#include <cstdint>

// ---------------- static device scratch (no allocs allowed) ----------------
#define MAXR   32
#define EPB    4096
#define MAXBLK 1024
#define MAXE   2000000
#define MAXN   200000
#define NFB    64          // blocks dedicated to feat->fp16 conversion

__device__ int g_blockhist[MAXBLK * MAXR];
__device__ int g_blockbase[MAXBLK * MAXR];
__device__ int g_off[MAXR + 1];   // edge offsets per relation
__device__ int g_gs[MAXR + 1];    // group (4-tile) offsets per relation
__device__ int2 g_srcdst[MAXE];   // packed {src, dst} in relation-sorted order
__device__ __align__(16) __half g_fh[MAXN * 64];       // feat as fp16
// Pre-packed B fragments (mma.m16n8k16 register order), fp16 hi/lo split.
// Layout: [rel][ks(4)][ntg(8)][lane(32)] -> uint2 {b0, b1}
__device__ __align__(16) uint2 g_wfh[MAXR * 1024];
__device__ __align__(16) uint2 g_wfl[MAXR * 1024];

// ---------------- helpers ----------------
__device__ __forceinline__ uint32_t smem_u32(const void* p) {
    uint32_t a;
    asm("{ .reg .u64 t; cvta.to.shared.u64 t, %1; cvt.u32.u64 %0, t; }"
        : "=r"(a) : "l"(p));
    return a;
}

__device__ __forceinline__ uint32_t pack_h2(__half a, __half b) {
    __half2 t = __halves2half2(a, b);
    return *reinterpret_cast<uint32_t*>(&t);
}

__device__ __forceinline__ void mma16816(float* c, const uint32_t* a, const uint32_t* b) {
    asm volatile(
        "mma.sync.aligned.m16n8k16.row.col.f32.f16.f16.f32 "
        "{%0,%1,%2,%3}, {%4,%5,%6,%7}, {%8,%9}, {%0,%1,%2,%3};"
        : "+f"(c[0]), "+f"(c[1]), "+f"(c[2]), "+f"(c[3])
        : "r"(a[0]), "r"(a[1]), "r"(a[2]), "r"(a[3]), "r"(b[0]), "r"(b[1]));
}

__device__ __forceinline__ void ldsm4(uint32_t* r, uint32_t addr) {
    asm volatile("ldmatrix.sync.aligned.m8n8.x4.shared.b16 {%0,%1,%2,%3}, [%4];"
                 : "=r"(r[0]), "=r"(r[1]), "=r"(r[2]), "=r"(r[3]) : "r"(addr));
}

__device__ __forceinline__ void red4(float* p, float a, float b, float c, float d) {
    asm volatile("red.global.add.v4.f32 [%0], {%1, %2, %3, %4};"
                 :: "l"(p), "f"(a), "f"(b), "f"(c), "f"(d) : "memory");
}

__device__ __forceinline__ void cpasync16(uint32_t dst, const void* src) {
    asm volatile("cp.async.ca.shared.global [%0], [%1], 16;"
                 :: "r"(dst), "l"(src) : "memory");
}
#define CP_COMMIT() asm volatile("cp.async.commit_group;" ::: "memory")
#define CP_WAIT(N)  asm volatile("cp.async.wait_group %0;" :: "n"(N) : "memory")

// ---------------- fused prep: W-frags (fp16 hi/lo) + feat->fp16 + hist ------
// Block roles: [0,R) prepw, [R,R+NFB) prepf, [R+NFB, ...) per-block histogram.
__global__ void k_prep_hist(const float* __restrict__ w, const float* __restrict__ feat,
                            const int* __restrict__ et, int E, int R, int nfeat) {
    int bid = blockIdx.x;
    if (bid < R) {
        int r = bid;
        const float* wr = w + r * 4096;
        for (int idx = threadIdx.x; idx < 1024; idx += blockDim.x) {
            int lane = idx & 31, ntg = (idx >> 5) & 7, ks = idx >> 8;
            int h = ntg >> 2, nt = ntg & 3, q = lane >> 2;
            int n = h * 32 + (q >> 1) * 8 + nt * 2 + (q & 1);
            int k0 = ks * 16 + 2 * (lane & 3);
            float w00 = wr[k0 * 64 + n],       w01 = wr[(k0 + 1) * 64 + n];
            float w10 = wr[(k0 + 8) * 64 + n], w11 = wr[(k0 + 9) * 64 + n];
            __half h00 = __float2half_rn(w00), h01 = __float2half_rn(w01);
            __half h10 = __float2half_rn(w10), h11 = __float2half_rn(w11);
            __half l00 = __float2half_rn(w00 - __half2float(h00));
            __half l01 = __float2half_rn(w01 - __half2float(h01));
            __half l10 = __float2half_rn(w10 - __half2float(h10));
            __half l11 = __float2half_rn(w11 - __half2float(h11));
            g_wfh[r * 1024 + idx] = make_uint2(pack_h2(h00, h01), pack_h2(h10, h11));
            g_wfl[r * 1024 + idx] = make_uint2(pack_h2(l00, l01), pack_h2(l10, l11));
        }
    } else if (bid < R + NFB) {
        int total = nfeat;  // elements
        for (int i = (bid - R) * blockDim.x + threadIdx.x; i < total / 2;
             i += NFB * blockDim.x) {
            float2 v = ((const float2*)feat)[i];
            ((uint32_t*)g_fh)[i] = pack_h2(__float2half_rn(v.x), __float2half_rn(v.y));
        }
    } else {
        __shared__ int h[MAXR];
        int hb = bid - R - NFB;
        if (threadIdx.x < MAXR) h[threadIdx.x] = 0;
        __syncthreads();
        int start = hb * EPB, end = min(start + EPB, E);
        for (int i = start + threadIdx.x; i < end; i += blockDim.x)
            atomicAdd(&h[et[i]], 1);
        __syncthreads();
        if (threadIdx.x < MAXR)
            g_blockhist[hb * MAXR + threadIdx.x] = h[threadIdx.x];
    }
}

// ---------------- scan + group offsets ----------------
__global__ void k_scan(int nblocks, int R) {
    __shared__ int tot[MAXR], off[MAXR + 1];
    int r = threadIdx.x;
    int s = 0;
    if (r < R)
        for (int b = 0; b < nblocks; b++) s += g_blockhist[b * MAXR + r];
    if (r < MAXR) tot[r] = s;
    __syncwarp();
    if (r == 0) {
        int acc = 0;
        for (int i = 0; i < R; i++) { off[i] = acc; acc += tot[i]; }
        off[R] = acc;
        int gs = 0;
        for (int i = 0; i < R; i++) {
            g_gs[i] = gs;
            int tiles = (tot[i] + 127) >> 7;
            gs += (tiles + 3) >> 2;           // groups of 4 tiles
        }
        g_gs[R] = gs;
        for (int i = 0; i <= R; i++) g_off[i] = off[i];
    }
    __syncwarp();
    if (r < R) {
        int base = off[r];
        for (int b = 0; b < nblocks; b++) {
            g_blockbase[b * MAXR + r] = base;
            base += g_blockhist[b * MAXR + r];
        }
    }
}

__global__ void k_scatter(const int* __restrict__ et, const int* __restrict__ src,
                          const int* __restrict__ dst, int E) {
    __shared__ int cur[MAXR];
    if (threadIdx.x < MAXR)
        cur[threadIdx.x] = g_blockbase[blockIdx.x * MAXR + threadIdx.x];
    __syncthreads();
    int start = blockIdx.x * EPB, end = min(start + EPB, E);
    for (int i = start + threadIdx.x; i < end; i += blockDim.x) {
        int p = atomicAdd(&cur[et[i]], 1);
        g_srcdst[p] = make_int2(src[i], dst[i]);
    }
}

// ---------------- main ----------------
// SMEM: A fp16 128x128B double-buffered (XOR-swizzled 16B chunks);
// B frag hi 8KB + lo 8KB; dst double-buffered; ctrl.
#define SM_A0   0
#define SM_A1   16384
#define SM_BH   32768
#define SM_BL   40960
#define SM_DST0 49152
#define SM_DST1 49664
#define SM_CTRL 50176
#define SMEM_SZ 50192

__global__ __launch_bounds__(256, 3) void k_main(float* __restrict__ out, int R)
{
    extern __shared__ char smem[];
    int tid = threadIdx.x;

    if ((int)blockIdx.x >= g_gs[R]) return;

    uint32_t sbase = smem_u32(smem);
    int* ctrl = (int*)(smem + SM_CTRL);
    if (tid == 0) {
        int b = blockIdx.x, r = 0;
        while (b >= g_gs[r + 1]) r++;
        int tile0 = (b - g_gs[r]) * 4;
        int ebase = g_off[r] + tile0 * 128;
        int erem = g_off[r + 1] - ebase;
        ctrl[0] = r;
        ctrl[1] = ebase;
        ctrl[2] = erem;
        ctrl[3] = min(4, (erem + 127) >> 7);
    }
    __syncthreads();
    int rel = ctrl[0], ebase = ctrl[1], erem = ctrl[2], ntile = ctrl[3];

    // ---- prologue: B frags + tile-0 gather in one cp.async group ----
    {
        const char* gh = (const char*)(g_wfh + (size_t)rel * 1024);
        const char* gl = (const char*)(g_wfl + (size_t)rel * 1024);
        int o = tid * 16;
        cpasync16(sbase + SM_BH + o, gh + o);
        cpasync16(sbase + SM_BH + 4096 + o, gh + 4096 + o);
        cpasync16(sbase + SM_BL + o, gl + o);
        cpasync16(sbase + SM_BL + 4096 + o, gl + 4096 + o);
    }
    {
        int row = tid >> 1, half = tid & 1;
        int cnt0 = min(128, erem);
        if (row < cnt0) {
            int2 e = g_srcdst[ebase + row];
            if (half == 0) ((int*)(smem + SM_DST0))[row] = e.y;
            const char* gp = (const char*)(g_fh + (size_t)e.x * 64);
#pragma unroll
            for (int i = 0; i < 4; i++) {
                int c = half * 4 + i;
                cpasync16(sbase + SM_A0 + row * 128 + ((c ^ (row & 7)) << 4),
                          gp + c * 16);
            }
        } else {
            if (half == 0) ((int*)(smem + SM_DST0))[row] = 0;
            uint4 z = make_uint4(0, 0, 0, 0);
#pragma unroll
            for (int i = 0; i < 4; i++) {
                int c = half * 4 + i;
                *(uint4*)(smem + SM_A0 + row * 128 + ((c ^ (row & 7)) << 4)) = z;
            }
        }
    }
    CP_COMMIT();

    int w = tid >> 5, lane = tid & 31;
    int mrow = (w & 3) * 32, h = w >> 2;
    int q = lane >> 2, m = lane & 3;
    // ldmatrix row/lane mapping (verified pattern from R2)
    int lrow = (lane & 7) + ((lane >> 3) & 1) * 8;
    int lkh = lane >> 4;

    for (int t = 0; t < ntile; t++) {
        int cnt = min(128, erem - t * 128);
        int abuf = (t & 1) ? SM_A1 : SM_A0;
        int dbuf = (t & 1) ? SM_DST1 : SM_DST0;

        // prefetch tile t+1 into the other buffer
        if (t + 1 < ntile) {
            int nbuf = ((t + 1) & 1) ? SM_A1 : SM_A0;
            int ndst = ((t + 1) & 1) ? SM_DST1 : SM_DST0;
            int cnt1 = min(128, erem - (t + 1) * 128);
            int row = tid >> 1, half = tid & 1;
            if (row < cnt1) {
                int2 e = g_srcdst[ebase + (t + 1) * 128 + row];
                if (half == 0) ((int*)(smem + ndst))[row] = e.y;
                const char* gp = (const char*)(g_fh + (size_t)e.x * 64);
#pragma unroll
                for (int i = 0; i < 4; i++) {
                    int c = half * 4 + i;
                    cpasync16(sbase + nbuf + row * 128 + ((c ^ (row & 7)) << 4),
                              gp + c * 16);
                }
            } else {
                if (half == 0) ((int*)(smem + ndst))[row] = 0;
                uint4 z = make_uint4(0, 0, 0, 0);
#pragma unroll
                for (int i = 0; i < 4; i++) {
                    int c = half * 4 + i;
                    *(uint4*)(smem + nbuf + row * 128 + ((c ^ (row & 7)) << 4)) = z;
                }
            }
            CP_COMMIT();
            CP_WAIT(1);     // tile t (and B) complete
        } else {
            CP_WAIT(0);
        }
        __syncthreads();

        // ---- compute: warp tile 32 rows x 32 cols, 2-term fp16 ----
        float acc[2][4][4];
#pragma unroll
        for (int a = 0; a < 2; a++)
#pragma unroll
            for (int b = 0; b < 4; b++)
#pragma unroll
                for (int c = 0; c < 4; c++) acc[a][b][c] = 0.0f;

#pragma unroll
        for (int ks = 0; ks < 4; ks++) {
            int kchunk = ks * 2 + lkh;
            uint32_t af[2][4];
#pragma unroll
            for (int mt = 0; mt < 2; mt++) {
                int arow = mrow + mt * 16 + lrow;
                ldsm4(af[mt], sbase + abuf + arow * 128 + ((kchunk ^ (arow & 7)) << 4));
            }
            const uint2* Bh = (const uint2*)(smem + SM_BH) + (ks * 8 + h * 4) * 32 + lane;
            const uint2* Bl = (const uint2*)(smem + SM_BL) + (ks * 8 + h * 4) * 32 + lane;
#pragma unroll
            for (int nt = 0; nt < 4; nt++) {
                uint2 bh = Bh[nt * 32];
                uint2 bl = Bl[nt * 32];
#pragma unroll
                for (int mt = 0; mt < 2; mt++) {
                    mma16816(acc[mt][nt], af[mt], (const uint32_t*)&bh);  // F*Wh
                    mma16816(acc[mt][nt], af[mt], (const uint32_t*)&bl);  // F*Wl
                }
            }
        }

        // ---- epilogue: 8 red.v4 per thread, 8 consecutive cols per row ----
        const int* db = (const int*)(smem + dbuf);
#pragma unroll
        for (int mt = 0; mt < 2; mt++)
#pragma unroll
            for (int hf = 0; hf < 2; hf++) {
                int row = mrow + mt * 16 + hf * 8 + q;
                if (row < cnt) {
                    int j = hf * 2;
                    float* o = out + (size_t)db[row] * 64 + h * 32 + m * 8;
                    red4(o,     acc[mt][0][j], acc[mt][0][j + 1],
                                acc[mt][1][j], acc[mt][1][j + 1]);
                    red4(o + 4, acc[mt][2][j], acc[mt][2][j + 1],
                                acc[mt][3][j], acc[mt][3][j + 1]);
                }
            }
        __syncthreads();   // buffer free before next prefetch overwrites it
    }
}

// ---------------- launch ----------------
extern "C" void kernel_launch(void* const* d_in, const int* in_sizes, int n_in,
                              void* d_out, int out_size) {
    const float* feat   = (const float*)d_in[0];
    const float* weight = (const float*)d_in[1];
    const int*   src    = (const int*)d_in[2];
    const int*   dst    = (const int*)d_in[3];
    const int*   et     = (const int*)d_in[4];

    int E = in_sizes[2];
    int R = in_sizes[1] / 4096;   // 64*64 per relation
    int nfeat = in_sizes[0];
    float* out = (float*)d_out;

    cudaMemsetAsync(out, 0, (size_t)out_size * sizeof(float), 0);

    int nblocks = (E + EPB - 1) / EPB;
    k_prep_hist<<<R + NFB + nblocks, 256>>>(weight, feat, et, E, R, nfeat);
    k_scan<<<1, 32>>>(nblocks, R);
    k_scatter<<<nblocks, 256>>>(et, src, dst, E);

    int ngroups = (E + 511) / 512 + R;   // upper bound; extras exit via g_gs[R]
    static int smem_set = 0;
    if (!smem_set) {
        cudaFuncSetAttribute(k_main, cudaFuncAttributeMaxDynamicSharedMemorySize, SMEM_SZ);
        smem_set = 1;
    }
    k_main<<<ngroups, 256, SMEM_SZ>>>(out, R);
}